// round 4
// baseline (speedup 1.0000x reference)
#include <cuda_runtime.h>
#include <math.h>
#include <stdint.h>

// Problem constants (fixed by setup_inputs)
#define NN 131072      // nodes
#define NE 2097152     // edges
#define NG 2048        // graphs
#define DIN 64         // input_dim
#define DH  128        // hidden dim

// ---------------- scratch (device globals; no allocation allowed) ----------
__device__ float g_hA[(size_t)NN * DH];
__device__ float g_hB[(size_t)NN * DH];
__device__ float g_agg[(size_t)NN * DH];
__device__ float g_hfc[(size_t)NN * DIN];
__device__ float g_gi[(size_t)NN * 3];
__device__ int   g_deg[NN];
__device__ int   g_off[NN + 1];
__device__ int   g_cur[NN];
__device__ int   g_src[NE];

__device__ __forceinline__ float gelu_exact(float x) {
    return 0.5f * x * (1.0f + erff(x * 0.70710678118654752f));
}

// ---------------- 1. embed + concat + L2 normalize -> g_hA ------------------
// x: [NN, 65] (last col = node id), emb: [5000, 64]. One warp per node.
__global__ void embed_norm_kernel(const float* __restrict__ x,
                                  const float* __restrict__ emb,
                                  float* __restrict__ hout) {
    int idx  = blockIdx.x * blockDim.x + threadIdx.x;
    int node = idx >> 5;
    int lane = idx & 31;
    if (node >= NN) return;

    const float* xr = x + (size_t)node * 65;
    int id = (int)xr[64];

    float v[4];
    int base = lane * 4;
#pragma unroll
    for (int j = 0; j < 4; j++) {
        int c = base + j;
        v[j] = (c < 64) ? xr[c] : emb[(size_t)id * 64 + (c - 64)];
    }
    float ss = v[0] * v[0] + v[1] * v[1] + v[2] * v[2] + v[3] * v[3];
#pragma unroll
    for (int o = 16; o > 0; o >>= 1) ss += __shfl_xor_sync(0xFFFFFFFFu, ss, o);
    float inv = 1.0f / sqrtf(ss);

    float4 o;
    o.x = v[0] * inv; o.y = v[1] * inv; o.z = v[2] * inv; o.w = v[3] * inv;
    *(float4*)&hout[(size_t)node * DH + base] = o;
}

// ---------------- 2. CSR build ----------------------------------------------
__global__ void zero_deg_kernel() {
    int i = blockIdx.x * blockDim.x + threadIdx.x;
    if (i < NN) g_deg[i] = 0;
}

__global__ void hist_kernel(const int* __restrict__ ei) {
    int e = blockIdx.x * blockDim.x + threadIdx.x;
    if (e < NE) atomicAdd(&g_deg[ei[NE + e]], 1);
}

// single-block scan: 1024 threads, 128 elements each
__global__ void scan_kernel() {
    __shared__ int sh[1024];
    const int CH = NN / 1024;  // 128
    int t = threadIdx.x;
    int base = t * CH;
    int s = 0;
    for (int i = 0; i < CH; i++) s += g_deg[base + i];
    sh[t] = s;
    __syncthreads();
    for (int d = 1; d < 1024; d <<= 1) {
        int v = 0;
        if (t >= d) v = sh[t - d];
        __syncthreads();
        sh[t] += v;
        __syncthreads();
    }
    int run = (t == 0) ? 0 : sh[t - 1];
    for (int i = 0; i < CH; i++) {
        g_off[base + i] = run;
        g_cur[base + i] = run;
        run += g_deg[base + i];
    }
    if (t == 1023) g_off[NN] = run;
}

__global__ void fill_kernel(const int* __restrict__ ei) {
    int e = blockIdx.x * blockDim.x + threadIdx.x;
    if (e < NE) {
        int s = ei[e];
        int d = ei[NE + e];
        int p = atomicAdd(&g_cur[d], 1);
        g_src[p] = s;
    }
}

// ---------------- 3. neighbor sum: agg[i] = sum_{j->i} h[j] ----------------
// One warp per node, each lane owns a float4 feature chunk.
__global__ void aggregate_kernel(const float* __restrict__ hin) {
    int idx  = blockIdx.x * blockDim.x + threadIdx.x;
    int node = idx >> 5;
    int lane = idx & 31;
    if (node >= NN) return;
    int beg = g_off[node], end = g_off[node + 1];
    float4 acc = make_float4(0.f, 0.f, 0.f, 0.f);
    for (int e = beg; e < end; e++) {
        int s = g_src[e];
        float4 v = __ldg((const float4*)&hin[(size_t)s * DH + lane * 4]);
        acc.x += v.x; acc.y += v.y; acc.z += v.z; acc.w += v.w;
    }
    *(float4*)&g_agg[(size_t)node * DH + lane * 4] = acc;
}

// ---------------- 4. GEMM (+optional second GEMM) + bias + GELU -------------
// C[i][c] = gelu( A1[i]@B1 (+ A2[i]@B2) + bias )
// A*: [NN,128] row-major. B*: [128,NC] row-major. M-tile 128, K-tile 32.
// 256 threads, each computes an 8x(NC/16) microtile.
template <int NC, bool DUAL>
__global__ __launch_bounds__(256, 2)
void gemm_gelu_kernel(const float* __restrict__ A1, const float* __restrict__ A2,
                      const float* __restrict__ B1, const float* __restrict__ B2,
                      const float* __restrict__ bias, float* __restrict__ C) {
    constexpr int CPT = NC / 16;             // cols per thread (8 or 4)
    constexpr int NKT = DUAL ? 8 : 4;        // k-tiles of 32
    __shared__ float As[32 * 132];           // A^T tile, padded stride 132 (16B aligned)
    __shared__ float Bs[32 * NC];

    int tid = threadIdx.x;
    int tx = tid & 15;     // col group
    int ty = tid >> 4;     // row group
    int M0 = blockIdx.x * 128;

    float acc[8][CPT];
#pragma unroll
    for (int r = 0; r < 8; r++)
#pragma unroll
        for (int c = 0; c < CPT; c++) acc[r][c] = 0.f;

    for (int kt = 0; kt < NKT; kt++) {
        const float* Asrc; const float* Bsrc; int kb;
        if (DUAL && kt >= 4) { Asrc = A2; Bsrc = B2; kb = (kt - 4) * 32; }
        else                 { Asrc = A1; Bsrc = B1; kb = kt * 32; }

        // stage global -> regs
        float4 av[4];
#pragma unroll
        for (int i = 0; i < 4; i++) {
            int f = tid + i * 256;          // 0..1023
            int m = f >> 3, kq = f & 7;
            av[i] = __ldg((const float4*)&Asrc[(size_t)(M0 + m) * 128 + kb + kq * 4]);
        }
        constexpr int BI = (32 * NC / 4) / 256;  // 4 (NC=128) or 2 (NC=64)
        float4 bv[BI];
#pragma unroll
        for (int i = 0; i < BI; i++) {
            int f = tid + i * 256;
            int k = f / (NC / 4), c4 = f % (NC / 4);
            bv[i] = __ldg((const float4*)&Bsrc[(size_t)(kb + k) * NC + c4 * 4]);
        }

        __syncthreads();   // previous tile's compute done
#pragma unroll
        for (int i = 0; i < 4; i++) {
            int f = tid + i * 256;
            int m = f >> 3, kq = f & 7;
            As[(kq * 4 + 0) * 132 + m] = av[i].x;
            As[(kq * 4 + 1) * 132 + m] = av[i].y;
            As[(kq * 4 + 2) * 132 + m] = av[i].z;
            As[(kq * 4 + 3) * 132 + m] = av[i].w;
        }
#pragma unroll
        for (int i = 0; i < BI; i++) {
            int f = tid + i * 256;
            int k = f / (NC / 4), c4 = f % (NC / 4);
            *(float4*)&Bs[k * NC + c4 * 4] = bv[i];
        }
        __syncthreads();

#pragma unroll 4
        for (int k = 0; k < 32; k++) {
            float a[8];
            float4 a0 = *(const float4*)&As[k * 132 + ty * 8];
            float4 a1 = *(const float4*)&As[k * 132 + ty * 8 + 4];
            a[0] = a0.x; a[1] = a0.y; a[2] = a0.z; a[3] = a0.w;
            a[4] = a1.x; a[5] = a1.y; a[6] = a1.z; a[7] = a1.w;
            float b[CPT];
            float4 b0 = *(const float4*)&Bs[k * NC + tx * CPT];
            b[0] = b0.x; b[1] = b0.y; b[2] = b0.z; b[3] = b0.w;
            if (CPT == 8) {
                float4 b1 = *(const float4*)&Bs[k * NC + tx * CPT + 4];
                b[4] = b1.x; b[5] = b1.y; b[6] = b1.z; b[7] = b1.w;
            }
#pragma unroll
            for (int r = 0; r < 8; r++)
#pragma unroll
                for (int c = 0; c < CPT; c++)
                    acc[r][c] += a[r] * b[c];
        }
    }

    // epilogue: bias + exact GELU
#pragma unroll
    for (int r = 0; r < 8; r++) {
        int row = M0 + ty * 8 + r;
#pragma unroll
        for (int c4 = 0; c4 < CPT / 4; c4++) {
            int cb = tx * CPT + c4 * 4;
            float4 o;
            o.x = gelu_exact(acc[r][c4 * 4 + 0] + bias[cb + 0]);
            o.y = gelu_exact(acc[r][c4 * 4 + 1] + bias[cb + 1]);
            o.z = gelu_exact(acc[r][c4 * 4 + 2] + bias[cb + 2]);
            o.w = gelu_exact(acc[r][c4 * 4 + 3] + bias[cb + 3]);
            *(float4*)&C[(size_t)row * NC + cb] = o;
        }
    }
}

// ---------------- 5. GRU input gates: gi[i][j] = hfc[i] . W_ih[j] + b_ih[j] -
__global__ void gi_kernel(const float* __restrict__ W_ih,
                          const float* __restrict__ b_ih) {
    int idx  = blockIdx.x * blockDim.x + threadIdx.x;
    int node = idx >> 5;
    int lane = idx & 31;
    if (node >= NN) return;
    float2 v = *(const float2*)&g_hfc[(size_t)node * DIN + lane * 2];
    float d0 = v.x * W_ih[lane * 2] + v.y * W_ih[lane * 2 + 1];
    float d1 = v.x * W_ih[64 + lane * 2] + v.y * W_ih[64 + lane * 2 + 1];
    float d2 = v.x * W_ih[128 + lane * 2] + v.y * W_ih[128 + lane * 2 + 1];
#pragma unroll
    for (int o = 16; o > 0; o >>= 1) {
        d0 += __shfl_xor_sync(0xFFFFFFFFu, d0, o);
        d1 += __shfl_xor_sync(0xFFFFFFFFu, d1, o);
        d2 += __shfl_xor_sync(0xFFFFFFFFu, d2, o);
    }
    if (lane == 0) {
        g_gi[(size_t)node * 3 + 0] = d0 + b_ih[0];
        g_gi[(size_t)node * 3 + 1] = d1 + b_ih[1];
        g_gi[(size_t)node * 3 + 2] = d2 + b_ih[2];
    }
}

// ---------------- 6. GRU scan (H=1) + last-nonzero select -------------------
__global__ void gru_scan_kernel(const float* __restrict__ W_hh,
                                const float* __restrict__ b_hh,
                                const float* __restrict__ init,
                                float* __restrict__ out) {
    int g = blockIdx.x * blockDim.x + threadIdx.x;
    if (g >= NG) return;
    float whr = W_hh[0], whz = W_hh[1], whn = W_hh[2];
    float bhr = b_hh[0], bhz = b_hh[1], bhn = b_hh[2];
    float h = init[0];
    float v0 = 0.f, lastVal = 0.f, sum = 0.f;
    int lastIdx = -1;
    const float* gp = &g_gi[(size_t)g * 64 * 3];
    for (int t = 0; t < 64; t++) {
        float gir = gp[t * 3 + 0];
        float giz = gp[t * 3 + 1];
        float gin = gp[t * 3 + 2];
        float r = 1.0f / (1.0f + expf(-(gir + whr * h + bhr)));
        float z = 1.0f / (1.0f + expf(-(giz + whz * h + bhz)));
        float n = tanhf(gin + r * (whn * h + bhn));
        h = (1.0f - z) * n + z * h;
        float m = h;  // mask == 1 (every graph has exactly 64 nodes)
        if (t == 0) v0 = m;
        if (m != 0.0f) { lastIdx = t; lastVal = m; }
        sum += m;
    }
    out[g] = (sum > 0.0f && lastIdx >= 0) ? lastVal : v0;
}

// ---------------- launch -----------------------------------------------------
extern "C" void kernel_launch(void* const* d_in, const int* in_sizes, int n_in,
                              void* d_out, int out_size) {
    (void)in_sizes; (void)n_in; (void)out_size;

    const float* x       = (const float*)d_in[0];
    const float* emb     = (const float*)d_in[1];
    const float* W_rel1  = (const float*)d_in[2];
    const float* b_rel1  = (const float*)d_in[3];
    const float* W_root1 = (const float*)d_in[4];
    const float* W_rel2  = (const float*)d_in[5];
    const float* b_rel2  = (const float*)d_in[6];
    const float* W_root2 = (const float*)d_in[7];
    const float* W_rel3  = (const float*)d_in[8];
    const float* b_rel3  = (const float*)d_in[9];
    const float* W_root3 = (const float*)d_in[10];
    const float* W_fc    = (const float*)d_in[11];
    const float* b_fc    = (const float*)d_in[12];
    const float* W_ih    = (const float*)d_in[13];
    const float* W_hh    = (const float*)d_in[14];
    const float* b_ih    = (const float*)d_in[15];
    const float* b_hh    = (const float*)d_in[16];
    const float* init    = (const float*)d_in[17];
    const int*   ei      = (const int*)d_in[18];
    float*       out     = (float*)d_out;

    float *hA, *hB, *agg, *hfc;
    cudaGetSymbolAddress((void**)&hA,  g_hA);
    cudaGetSymbolAddress((void**)&hB,  g_hB);
    cudaGetSymbolAddress((void**)&agg, g_agg);
    cudaGetSymbolAddress((void**)&hfc, g_hfc);

    const int T = 256;

    // embedding + normalize, CSR build
    zero_deg_kernel<<<(NN + T - 1) / T, T>>>();
    embed_norm_kernel<<<NN / 8, T>>>(x, emb, hA);
    hist_kernel<<<NE / T, T>>>(ei);
    scan_kernel<<<1, 1024>>>();
    fill_kernel<<<NE / T, T>>>(ei);

    // conv1: hA -> hB
    aggregate_kernel<<<NN / 8, T>>>(hA);
    gemm_gelu_kernel<128, true><<<NN / 128, T>>>(agg, hA, W_rel1, W_root1, b_rel1, hB);
    // conv2: hB -> hA
    aggregate_kernel<<<NN / 8, T>>>(hB);
    gemm_gelu_kernel<128, true><<<NN / 128, T>>>(agg, hB, W_rel2, W_root2, b_rel2, hA);
    // conv3: hA -> hB
    aggregate_kernel<<<NN / 8, T>>>(hA);
    gemm_gelu_kernel<128, true><<<NN / 128, T>>>(agg, hA, W_rel3, W_root3, b_rel3, hB);
    // fc: hB -> hfc
    gemm_gelu_kernel<64, false><<<NN / 128, T>>>(hB, nullptr, W_fc, nullptr, b_fc, hfc);

    // GRU
    gi_kernel<<<NN / 8, T>>>(W_ih, b_ih);
    gru_scan_kernel<<<NG / T, T>>>(W_hh, b_hh, init, out);
}

// round 5
// speedup vs baseline: 1.3502x; 1.3502x over previous
#include <cuda_runtime.h>
#include <math.h>
#include <stdint.h>

// Problem constants (fixed by setup_inputs)
#define NN 131072      // nodes
#define NE 2097152     // edges
#define NG 2048        // graphs
#define DIN 64         // input_dim
#define DH  128        // hidden dim

#define SCAN_BLOCKS 512
#define SCAN_TPB    256          // SCAN_BLOCKS * SCAN_TPB == NN

// ---------------- scratch (device globals; no allocation allowed) ----------
__device__ float g_hA[(size_t)NN * DH];
__device__ float g_hB[(size_t)NN * DH];
__device__ float g_agg[(size_t)NN * DH];
__device__ float g_hfc[(size_t)NN * DIN];
__device__ float g_gi[(size_t)NN * 3];
__device__ int   g_deg[NN];
__device__ int   g_off[NN + 1];
__device__ int   g_cur[NN];
__device__ int   g_src[NE];
__device__ int   g_bsum[SCAN_BLOCKS];
__device__ int   g_boff[SCAN_BLOCKS];

__device__ __forceinline__ float gelu_exact(float x) {
    return 0.5f * x * (1.0f + erff(x * 0.70710678118654752f));
}

// ---------------- 1. embed + concat + L2 normalize -> g_hA ------------------
// x: [NN, 65] (last col = node id), emb: [5000, 64]. One warp per node.
__global__ void embed_norm_kernel(const float* __restrict__ x,
                                  const float* __restrict__ emb,
                                  float* __restrict__ hout) {
    int idx  = blockIdx.x * blockDim.x + threadIdx.x;
    int node = idx >> 5;
    int lane = idx & 31;
    if (node >= NN) return;

    const float* xr = x + (size_t)node * 65;
    int id = (int)xr[64];

    float v[4];
    int base = lane * 4;
#pragma unroll
    for (int j = 0; j < 4; j++) {
        int c = base + j;
        v[j] = (c < 64) ? xr[c] : emb[(size_t)id * 64 + (c - 64)];
    }
    float ss = v[0] * v[0] + v[1] * v[1] + v[2] * v[2] + v[3] * v[3];
#pragma unroll
    for (int o = 16; o > 0; o >>= 1) ss += __shfl_xor_sync(0xFFFFFFFFu, ss, o);
    float inv = 1.0f / sqrtf(ss);

    float4 o;
    o.x = v[0] * inv; o.y = v[1] * inv; o.z = v[2] * inv; o.w = v[3] * inv;
    *(float4*)&hout[(size_t)node * DH + base] = o;
}

// ---------------- 2. CSR build ----------------------------------------------
__global__ void zero_deg_kernel() {
    int i = blockIdx.x * blockDim.x + threadIdx.x;
    if (i < NN) g_deg[i] = 0;
}

__global__ void hist_kernel(const int* __restrict__ ei) {
    int e = blockIdx.x * blockDim.x + threadIdx.x;
    if (e < NE) atomicAdd(&g_deg[ei[NE + e]], 1);
}

// --- chip-wide 3-phase exclusive scan of g_deg -> g_off / g_cur -------------
// Phase 1: per-block reduction of 256 degrees.
__global__ void scan_phase1() {
    __shared__ int sh[SCAN_TPB];
    int b = blockIdx.x, t = threadIdx.x;
    sh[t] = g_deg[b * SCAN_TPB + t];
    __syncthreads();
#pragma unroll
    for (int d = SCAN_TPB / 2; d > 0; d >>= 1) {
        if (t < d) sh[t] += sh[t + d];
        __syncthreads();
    }
    if (t == 0) g_bsum[b] = sh[0];
}

// Phase 2: single block, exclusive scan of the 512 block sums.
__global__ void scan_phase2() {
    __shared__ int sh[SCAN_BLOCKS];
    int t = threadIdx.x;
    sh[t] = g_bsum[t];
    __syncthreads();
#pragma unroll
    for (int d = 1; d < SCAN_BLOCKS; d <<= 1) {
        int v = (t >= d) ? sh[t - d] : 0;
        __syncthreads();
        sh[t] += v;
        __syncthreads();
    }
    g_boff[t] = (t == 0) ? 0 : sh[t - 1];
}

// Phase 3: per-block inclusive scan + block offset -> offsets.
__global__ void scan_phase3() {
    __shared__ int sh[SCAN_TPB];
    int b = blockIdx.x, t = threadIdx.x;
    int i = b * SCAN_TPB + t;
    int d = g_deg[i];
    sh[t] = d;
    __syncthreads();
#pragma unroll
    for (int s = 1; s < SCAN_TPB; s <<= 1) {
        int v = (t >= s) ? sh[t - s] : 0;
        __syncthreads();
        sh[t] += v;
        __syncthreads();
    }
    int off = g_boff[b] + sh[t] - d;   // exclusive
    g_off[i] = off;
    g_cur[i] = off;
    if (i == NN - 1) g_off[NN] = off + d;
}

__global__ void fill_kernel(const int* __restrict__ ei) {
    int e = blockIdx.x * blockDim.x + threadIdx.x;
    if (e < NE) {
        int s = ei[e];
        int d = ei[NE + e];
        int p = atomicAdd(&g_cur[d], 1);
        g_src[p] = s;
    }
}

// ---------------- 3. neighbor sum: agg[i] = sum_{j->i} h[j] ----------------
// One warp per node, each lane owns a float4 feature chunk.
__global__ void aggregate_kernel(const float* __restrict__ hin) {
    int idx  = blockIdx.x * blockDim.x + threadIdx.x;
    int node = idx >> 5;
    int lane = idx & 31;
    if (node >= NN) return;
    int beg = g_off[node], end = g_off[node + 1];
    float4 acc = make_float4(0.f, 0.f, 0.f, 0.f);
    int e = beg;
#pragma unroll 1
    for (; e + 4 <= end; e += 4) {
        int s0 = g_src[e], s1 = g_src[e + 1], s2 = g_src[e + 2], s3 = g_src[e + 3];
        float4 v0 = __ldg((const float4*)&hin[(size_t)s0 * DH + lane * 4]);
        float4 v1 = __ldg((const float4*)&hin[(size_t)s1 * DH + lane * 4]);
        float4 v2 = __ldg((const float4*)&hin[(size_t)s2 * DH + lane * 4]);
        float4 v3 = __ldg((const float4*)&hin[(size_t)s3 * DH + lane * 4]);
        acc.x += v0.x; acc.y += v0.y; acc.z += v0.z; acc.w += v0.w;
        acc.x += v1.x; acc.y += v1.y; acc.z += v1.z; acc.w += v1.w;
        acc.x += v2.x; acc.y += v2.y; acc.z += v2.z; acc.w += v2.w;
        acc.x += v3.x; acc.y += v3.y; acc.z += v3.z; acc.w += v3.w;
    }
    for (; e < end; e++) {
        int s = g_src[e];
        float4 v = __ldg((const float4*)&hin[(size_t)s * DH + lane * 4]);
        acc.x += v.x; acc.y += v.y; acc.z += v.z; acc.w += v.w;
    }
    *(float4*)&g_agg[(size_t)node * DH + lane * 4] = acc;
}

// ---------------- 4. GEMM (+optional second GEMM) + bias + GELU -------------
// C[i][c] = gelu( A1[i]@B1 (+ A2[i]@B2) + bias )
// A*: [NN,128] row-major. B*: [128,NC] row-major. M-tile 128, K-tile 32.
// 256 threads, each computes an 8x(NC/16) microtile.
template <int NC, bool DUAL>
__global__ __launch_bounds__(256, 2)
void gemm_gelu_kernel(const float* __restrict__ A1, const float* __restrict__ A2,
                      const float* __restrict__ B1, const float* __restrict__ B2,
                      const float* __restrict__ bias, float* __restrict__ C) {
    constexpr int CPT = NC / 16;             // cols per thread (8 or 4)
    constexpr int NKT = DUAL ? 8 : 4;        // k-tiles of 32
    __shared__ float As[32 * 132];           // A^T tile, padded stride 132 (16B aligned)
    __shared__ float Bs[32 * NC];

    int tid = threadIdx.x;
    int tx = tid & 15;     // col group
    int ty = tid >> 4;     // row group
    int M0 = blockIdx.x * 128;

    float acc[8][CPT];
#pragma unroll
    for (int r = 0; r < 8; r++)
#pragma unroll
        for (int c = 0; c < CPT; c++) acc[r][c] = 0.f;

    for (int kt = 0; kt < NKT; kt++) {
        const float* Asrc; const float* Bsrc; int kb;
        if (DUAL && kt >= 4) { Asrc = A2; Bsrc = B2; kb = (kt - 4) * 32; }
        else                 { Asrc = A1; Bsrc = B1; kb = kt * 32; }

        // stage global -> regs
        float4 av[4];
#pragma unroll
        for (int i = 0; i < 4; i++) {
            int f = tid + i * 256;          // 0..1023
            int m = f >> 3, kq = f & 7;
            av[i] = __ldg((const float4*)&Asrc[(size_t)(M0 + m) * 128 + kb + kq * 4]);
        }
        constexpr int BI = (32 * NC / 4) / 256;  // 4 (NC=128) or 2 (NC=64)
        float4 bv[BI];
#pragma unroll
        for (int i = 0; i < BI; i++) {
            int f = tid + i * 256;
            int k = f / (NC / 4), c4 = f % (NC / 4);
            bv[i] = __ldg((const float4*)&Bsrc[(size_t)(kb + k) * NC + c4 * 4]);
        }

        __syncthreads();   // previous tile's compute done
#pragma unroll
        for (int i = 0; i < 4; i++) {
            int f = tid + i * 256;
            int m = f >> 3, kq = f & 7;
            As[(kq * 4 + 0) * 132 + m] = av[i].x;
            As[(kq * 4 + 1) * 132 + m] = av[i].y;
            As[(kq * 4 + 2) * 132 + m] = av[i].z;
            As[(kq * 4 + 3) * 132 + m] = av[i].w;
        }
#pragma unroll
        for (int i = 0; i < BI; i++) {
            int f = tid + i * 256;
            int k = f / (NC / 4), c4 = f % (NC / 4);
            *(float4*)&Bs[k * NC + c4 * 4] = bv[i];
        }
        __syncthreads();

#pragma unroll 4
        for (int k = 0; k < 32; k++) {
            float a[8];
            float4 a0 = *(const float4*)&As[k * 132 + ty * 8];
            float4 a1 = *(const float4*)&As[k * 132 + ty * 8 + 4];
            a[0] = a0.x; a[1] = a0.y; a[2] = a0.z; a[3] = a0.w;
            a[4] = a1.x; a[5] = a1.y; a[6] = a1.z; a[7] = a1.w;
            float b[CPT];
            float4 b0 = *(const float4*)&Bs[k * NC + tx * CPT];
            b[0] = b0.x; b[1] = b0.y; b[2] = b0.z; b[3] = b0.w;
            if (CPT == 8) {
                float4 b1 = *(const float4*)&Bs[k * NC + tx * CPT + 4];
                b[4] = b1.x; b[5] = b1.y; b[6] = b1.z; b[7] = b1.w;
            }
#pragma unroll
            for (int r = 0; r < 8; r++)
#pragma unroll
                for (int c = 0; c < CPT; c++)
                    acc[r][c] += a[r] * b[c];
        }
    }

    // epilogue: bias + exact GELU
#pragma unroll
    for (int r = 0; r < 8; r++) {
        int row = M0 + ty * 8 + r;
#pragma unroll
        for (int c4 = 0; c4 < CPT / 4; c4++) {
            int cb = tx * CPT + c4 * 4;
            float4 o;
            o.x = gelu_exact(acc[r][c4 * 4 + 0] + bias[cb + 0]);
            o.y = gelu_exact(acc[r][c4 * 4 + 1] + bias[cb + 1]);
            o.z = gelu_exact(acc[r][c4 * 4 + 2] + bias[cb + 2]);
            o.w = gelu_exact(acc[r][c4 * 4 + 3] + bias[cb + 3]);
            *(float4*)&C[(size_t)row * NC + cb] = o;
        }
    }
}

// ---------------- 5. GRU input gates: gi[i][j] = hfc[i] . W_ih[j] + b_ih[j] -
__global__ void gi_kernel(const float* __restrict__ W_ih,
                          const float* __restrict__ b_ih) {
    int idx  = blockIdx.x * blockDim.x + threadIdx.x;
    int node = idx >> 5;
    int lane = idx & 31;
    if (node >= NN) return;
    float2 v = *(const float2*)&g_hfc[(size_t)node * DIN + lane * 2];
    float d0 = v.x * W_ih[lane * 2] + v.y * W_ih[lane * 2 + 1];
    float d1 = v.x * W_ih[64 + lane * 2] + v.y * W_ih[64 + lane * 2 + 1];
    float d2 = v.x * W_ih[128 + lane * 2] + v.y * W_ih[128 + lane * 2 + 1];
#pragma unroll
    for (int o = 16; o > 0; o >>= 1) {
        d0 += __shfl_xor_sync(0xFFFFFFFFu, d0, o);
        d1 += __shfl_xor_sync(0xFFFFFFFFu, d1, o);
        d2 += __shfl_xor_sync(0xFFFFFFFFu, d2, o);
    }
    if (lane == 0) {
        g_gi[(size_t)node * 3 + 0] = d0 + b_ih[0];
        g_gi[(size_t)node * 3 + 1] = d1 + b_ih[1];
        g_gi[(size_t)node * 3 + 2] = d2 + b_ih[2];
    }
}

// ---------------- 6. GRU scan (H=1) + last-nonzero select -------------------
__global__ void gru_scan_kernel(const float* __restrict__ W_hh,
                                const float* __restrict__ b_hh,
                                const float* __restrict__ init,
                                float* __restrict__ out) {
    int g = blockIdx.x * blockDim.x + threadIdx.x;
    if (g >= NG) return;
    float whr = W_hh[0], whz = W_hh[1], whn = W_hh[2];
    float bhr = b_hh[0], bhz = b_hh[1], bhn = b_hh[2];
    float h = init[0];
    float v0 = 0.f, lastVal = 0.f, sum = 0.f;
    int lastIdx = -1;
    const float* gp = &g_gi[(size_t)g * 64 * 3];
    for (int t = 0; t < 64; t++) {
        float gir = gp[t * 3 + 0];
        float giz = gp[t * 3 + 1];
        float gin = gp[t * 3 + 2];
        float r = 1.0f / (1.0f + expf(-(gir + whr * h + bhr)));
        float z = 1.0f / (1.0f + expf(-(giz + whz * h + bhz)));
        float n = tanhf(gin + r * (whn * h + bhn));
        h = (1.0f - z) * n + z * h;
        float m = h;  // mask == 1 (every graph has exactly 64 nodes)
        if (t == 0) v0 = m;
        if (m != 0.0f) { lastIdx = t; lastVal = m; }
        sum += m;
    }
    out[g] = (sum > 0.0f && lastIdx >= 0) ? lastVal : v0;
}

// ---------------- launch -----------------------------------------------------
extern "C" void kernel_launch(void* const* d_in, const int* in_sizes, int n_in,
                              void* d_out, int out_size) {
    (void)in_sizes; (void)n_in; (void)out_size;

    const float* x       = (const float*)d_in[0];
    const float* emb     = (const float*)d_in[1];
    const float* W_rel1  = (const float*)d_in[2];
    const float* b_rel1  = (const float*)d_in[3];
    const float* W_root1 = (const float*)d_in[4];
    const float* W_rel2  = (const float*)d_in[5];
    const float* b_rel2  = (const float*)d_in[6];
    const float* W_root2 = (const float*)d_in[7];
    const float* W_rel3  = (const float*)d_in[8];
    const float* b_rel3  = (const float*)d_in[9];
    const float* W_root3 = (const float*)d_in[10];
    const float* W_fc    = (const float*)d_in[11];
    const float* b_fc    = (const float*)d_in[12];
    const float* W_ih    = (const float*)d_in[13];
    const float* W_hh    = (const float*)d_in[14];
    const float* b_ih    = (const float*)d_in[15];
    const float* b_hh    = (const float*)d_in[16];
    const float* init    = (const float*)d_in[17];
    const int*   ei      = (const int*)d_in[18];
    float*       out     = (float*)d_out;

    float *hA, *hB, *agg, *hfc;
    cudaGetSymbolAddress((void**)&hA,  g_hA);
    cudaGetSymbolAddress((void**)&hB,  g_hB);
    cudaGetSymbolAddress((void**)&agg, g_agg);
    cudaGetSymbolAddress((void**)&hfc, g_hfc);

    const int T = 256;

    // embedding + normalize, CSR build
    zero_deg_kernel<<<(NN + T - 1) / T, T>>>();
    embed_norm_kernel<<<NN / 8, T>>>(x, emb, hA);
    hist_kernel<<<NE / T, T>>>(ei);
    scan_phase1<<<SCAN_BLOCKS, SCAN_TPB>>>();
    scan_phase2<<<1, SCAN_BLOCKS>>>();
    scan_phase3<<<SCAN_BLOCKS, SCAN_TPB>>>();
    fill_kernel<<<NE / T, T>>>(ei);

    // conv1: hA -> hB
    aggregate_kernel<<<NN / 8, T>>>(hA);
    gemm_gelu_kernel<128, true><<<NN / 128, T>>>(agg, hA, W_rel1, W_root1, b_rel1, hB);
    // conv2: hB -> hA
    aggregate_kernel<<<NN / 8, T>>>(hB);
    gemm_gelu_kernel<128, true><<<NN / 128, T>>>(agg, hB, W_rel2, W_root2, b_rel2, hA);
    // conv3: hA -> hB
    aggregate_kernel<<<NN / 8, T>>>(hA);
    gemm_gelu_kernel<128, true><<<NN / 128, T>>>(agg, hA, W_rel3, W_root3, b_rel3, hB);
    // fc: hB -> hfc
    gemm_gelu_kernel<64, false><<<NN / 128, T>>>(hB, nullptr, W_fc, nullptr, b_fc, hfc);

    // GRU
    gi_kernel<<<NN / 8, T>>>(W_ih, b_ih);
    gru_scan_kernel<<<NG / T, T>>>(W_hh, b_hh, init, out);
}